// round 3
// baseline (speedup 1.0000x reference)
#include <cuda_runtime.h>
#include <math.h>

// Problem dims
#define B_   32
#define L_   512
#define E_   1024
#define H_   1024
#define P_   512
#define G4H_ (4 * H_)

// Scan kernel config
#define NBLK 128
#define NTHR 256
#define JPB  8   // hidden units per CTA (H_/NBLK)
#define PPB  4   // projection rows per CTA (P_/NBLK)

// Dynamic shared memory layout for scan kernel (in floats)
#define HS_PITCH 36
#define HS_OFF   0
#define WS_OFF   (512 * HS_PITCH)              // 18432
#define WR_OFF   (WS_OFF + 512 * HS_PITCH)     // 36864
#define RED_OFF  (WR_OFF + H_ * 4)             // 40960
#define SMEM_FLOATS (RED_OFF + 4 * 32 * 33)    // 45184
#define SMEM_BYTES  (SMEM_FLOATS * 4)          // 180736 bytes

// Scratch (device globals; no cudaMalloc allowed)
__device__ float    g_xg[(size_t)B_ * L_ * G4H_];   // [B*L, 4H] precomputed input gates
__device__ float    g_m[H_ * B_];                   // [H][B] m = o*tanh(c) exchange buffer
__device__ unsigned g_arrive;
__device__ unsigned g_release;

__global__ void init_bar_kernel() {
    g_arrive  = 0u;
    g_release = 0u;
}

// ---------------------------------------------------------------------------
// Phase 1: xg[row, n] = sum_k x[row, k] * W_ih[n, k] + b_ih[n] + b_hh[n]
// M = B*L = 16384, N = 4H = 4096, K = E = 1024
// Tiled fp32 GEMM: BM=BN=128, BK=8, 256 threads, 8x8 microtile.
// ---------------------------------------------------------------------------
#define GBM 128
#define GBN 128
#define GBK 8
#define GPITCH 132

__global__ void __launch_bounds__(256)
gemm_xg_kernel(const float* __restrict__ A,     // x_emb [16384, 1024]
               const float* __restrict__ Wih,   // [4096, 1024]
               const float* __restrict__ bih,
               const float* __restrict__ bhh) {
    __shared__ float As[GBK][GPITCH];
    __shared__ float Bs[GBK][GPITCH];

    const int tid  = threadIdx.x;
    const int gn0  = blockIdx.x * GBN;
    const int gm0  = blockIdx.y * GBM;
    const int lrow = tid >> 1;          // 0..127
    const int lk4  = (tid & 1) * 4;     // 0 or 4
    const int ty   = tid >> 4;          // 0..15
    const int tx   = tid & 15;          // 0..15

    float acc[8][8];
#pragma unroll
    for (int i = 0; i < 8; i++)
#pragma unroll
        for (int j = 0; j < 8; j++) acc[i][j] = 0.0f;

    const float* Aptr = A   + (size_t)(gm0 + lrow) * E_ + lk4;
    const float* Bptr = Wih + (size_t)(gn0 + lrow) * E_ + lk4;

    for (int k0 = 0; k0 < E_; k0 += GBK) {
        float4 av = *reinterpret_cast<const float4*>(Aptr + k0);
        float4 bv = *reinterpret_cast<const float4*>(Bptr + k0);
        __syncthreads();
        As[lk4 + 0][lrow] = av.x;
        As[lk4 + 1][lrow] = av.y;
        As[lk4 + 2][lrow] = av.z;
        As[lk4 + 3][lrow] = av.w;
        Bs[lk4 + 0][lrow] = bv.x;
        Bs[lk4 + 1][lrow] = bv.y;
        Bs[lk4 + 2][lrow] = bv.z;
        Bs[lk4 + 3][lrow] = bv.w;
        __syncthreads();
#pragma unroll
        for (int kk = 0; kk < GBK; kk++) {
            float4 a0 = *reinterpret_cast<const float4*>(&As[kk][ty * 8]);
            float4 a1 = *reinterpret_cast<const float4*>(&As[kk][ty * 8 + 4]);
            float4 b0 = *reinterpret_cast<const float4*>(&Bs[kk][tx * 8]);
            float4 b1 = *reinterpret_cast<const float4*>(&Bs[kk][tx * 8 + 4]);
            float ar[8] = {a0.x, a0.y, a0.z, a0.w, a1.x, a1.y, a1.z, a1.w};
            float br[8] = {b0.x, b0.y, b0.z, b0.w, b1.x, b1.y, b1.z, b1.w};
#pragma unroll
            for (int i = 0; i < 8; i++)
#pragma unroll
                for (int j = 0; j < 8; j++) acc[i][j] += ar[i] * br[j];
        }
    }

    float bias[8];
#pragma unroll
    for (int j = 0; j < 8; j++) {
        int n = gn0 + tx * 8 + j;
        bias[j] = bih[n] + bhh[n];
    }

#pragma unroll
    for (int i = 0; i < 8; i++) {
        size_t row = (size_t)(gm0 + ty * 8 + i);
        float4 v0, v1;
        v0.x = acc[i][0] + bias[0]; v0.y = acc[i][1] + bias[1];
        v0.z = acc[i][2] + bias[2]; v0.w = acc[i][3] + bias[3];
        v1.x = acc[i][4] + bias[4]; v1.y = acc[i][5] + bias[5];
        v1.z = acc[i][6] + bias[6]; v1.w = acc[i][7] + bias[7];
        *reinterpret_cast<float4*>(&g_xg[row * G4H_ + gn0 + tx * 8])     = v0;
        *reinterpret_cast<float4*>(&g_xg[row * G4H_ + gn0 + tx * 8 + 4]) = v1;
    }
}

// ---------------------------------------------------------------------------
// Grid-wide barrier (persistent kernel, 128 CTAs all co-resident).
// Release: last arriver publishes k. Waiters acquire with __threadfence()
// after the spin so cross-CTA data written before the barrier is visible.
// ---------------------------------------------------------------------------
__device__ __forceinline__ void grid_bar(unsigned k) {
    __syncthreads();
    if (threadIdx.x == 0) {
        __threadfence();
        unsigned prev = atomicAdd(&g_arrive, 1u);
        if (prev == k * (unsigned)gridDim.x - 1u) {
            *(volatile unsigned*)&g_release = k;
        } else {
            while (*(volatile unsigned*)&g_release < k) __nanosleep(32);
            __threadfence();   // acquire: order subsequent global reads
        }
    }
    __syncthreads();
}

__device__ __forceinline__ float sigmoidf_(float x) {
    return 1.0f / (1.0f + __expf(-x));
}

// ---------------------------------------------------------------------------
// Phase 2: recurrent scan. 128 persistent CTAs x 256 threads.
// CTA blk owns hidden units j = blk*8 .. blk*8+7 (their 32 W_hh rows in SMEM,
// cell states in registers) and projection rows p = blk*4 .. blk*4+3.
// ---------------------------------------------------------------------------
__global__ void __launch_bounds__(NTHR, 1)
lstm_scan_kernel(const float* __restrict__ Whh,   // [4096, 512]
                 const float* __restrict__ Whr,   // [512, 1024]
                 float* __restrict__ out) {       // [B, L, P]
    extern __shared__ float smem[];
    float* h_s  = smem + HS_OFF;   // [k=512][b=32] pitch 36
    float* w_s  = smem + WS_OFF;   // [k=512][c=32] pitch 36
    float* wr_s = smem + WR_OFF;   // [k=1024][pp=4]
    float* red  = smem + RED_OFF;  // [4][32][33] gates / [8*4*32] proj partials

    const int tid  = threadIdx.x;
    const int blk  = blockIdx.x;
    const int warp = tid >> 5;
    const int lane = tid & 31;

    // ---- preload W_hh slice into w_s[k][c], c = gate*8 + q
    for (int c = warp; c < 32; c += 8) {
        int gate = c >> 3, q = c & 7;
        const float* src = Whh + (size_t)(gate * H_ + blk * JPB + q) * P_;
        for (int k = lane; k < P_; k += 32) w_s[k * HS_PITCH + c] = src[k];
    }
    // ---- preload W_hr slice into wr_s[k][pp]
    for (int idx = tid; idx < PPB * H_; idx += NTHR) {
        int pp = idx >> 10;        // /H_
        int k  = idx & (H_ - 1);
        wr_s[k * 4 + pp] = Whr[(size_t)(blk * PPB + pp) * H_ + k];
    }
    __syncthreads();

    // persistent cell state: thread tid owns (b = tid>>3, q = tid&7)
    float cst = 0.0f;
    const int cb = tid >> 3;
    const int cq = tid & 7;

    // gate-GEMM identity: 4 K-split groups of 64 threads, 4x4 microtiles
    const int g4 = tid >> 6;        // 0..3, k in [g4*128, g4*128+128)
    const int id = tid & 63;
    const int ty = id >> 3;         // batches 4*ty..+3
    const int tx = id & 7;          // cols 4*tx..+3

    unsigned barno = 0;

    for (int t = 0; t < L_; ++t) {
        float acc[4][4];
#pragma unroll
        for (int i = 0; i < 4; i++)
#pragma unroll
            for (int j = 0; j < 4; j++) acc[i][j] = 0.0f;

        if (t > 0) {
            // stage h_{t-1} = out[:, t-1, :] into h_s[k][b] (L2 reads: __ldcg)
            for (int idx = tid; idx < B_ * P_; idx += NTHR) {
                int b = idx >> 9;           // /P_
                int k = idx & (P_ - 1);
                h_s[k * HS_PITCH + b] =
                    __ldcg(out + ((size_t)b * L_ + (t - 1)) * P_ + k);
            }
            __syncthreads();

            const int k0 = g4 * 128;
#pragma unroll 4
            for (int kk = 0; kk < 128; ++kk) {
                int k = k0 + kk;
                float4 hv = *reinterpret_cast<const float4*>(&h_s[k * HS_PITCH + 4 * ty]);
                float4 wv = *reinterpret_cast<const float4*>(&w_s[k * HS_PITCH + 4 * tx]);
                float hb[4] = {hv.x, hv.y, hv.z, hv.w};
                float wb[4] = {wv.x, wv.y, wv.z, wv.w};
#pragma unroll
                for (int i = 0; i < 4; i++)
#pragma unroll
                    for (int j = 0; j < 4; j++) acc[i][j] += hb[i] * wb[j];
            }
        }

        // write K-split partials: red[g4][b][c], pitch 33
#pragma unroll
        for (int i = 0; i < 4; i++)
#pragma unroll
            for (int j = 0; j < 4; j++)
                red[(g4 * 32 + 4 * ty + i) * 33 + 4 * tx + j] = acc[i][j];
        __syncthreads();

        // ---- cell update: thread owns (cb, cq)
        {
            float gsum[4];
#pragma unroll
            for (int gi = 0; gi < 4; ++gi) {
                int c = gi * 8 + cq;
                float s = red[(0 * 32 + cb) * 33 + c] + red[(1 * 32 + cb) * 33 + c] +
                          red[(2 * 32 + cb) * 33 + c] + red[(3 * 32 + cb) * 33 + c];
                s += g_xg[((size_t)cb * L_ + t) * G4H_ + gi * H_ + blk * JPB + cq];
                gsum[gi] = s;
            }
            float ig = sigmoidf_(gsum[0]);
            float fg = sigmoidf_(gsum[1]);
            float gg = tanhf(gsum[2]);
            float og = sigmoidf_(gsum[3]);
            cst = fg * cst + ig * gg;
            float m = og * tanhf(cst);
            g_m[(blk * JPB + cq) * B_ + cb] = m;
        }

        grid_bar(++barno);   // m visible chip-wide

        // ---- projection: warp w handles k in [w*128, w*128+128), lane = batch
        float pa[4] = {0.0f, 0.0f, 0.0f, 0.0f};
        {
            const int kbeg = warp * 128;
#pragma unroll 4
            for (int k = kbeg; k < kbeg + 128; ++k) {
                float  mv = __ldcg(&g_m[k * B_ + lane]);
                float4 wv = *reinterpret_cast<const float4*>(&wr_s[k * 4]);
                pa[0] += mv * wv.x;
                pa[1] += mv * wv.y;
                pa[2] += mv * wv.z;
                pa[3] += mv * wv.w;
            }
        }
        // reduce 8 warp partials via smem (reuse red)
#pragma unroll
        for (int p = 0; p < 4; p++) red[(warp * 4 + p) * 32 + lane] = pa[p];
        __syncthreads();
        if (tid < 128) {
            int p = tid >> 5;
            int b = tid & 31;
            float s = 0.0f;
#pragma unroll
            for (int w = 0; w < 8; w++) s += red[(w * 4 + p) * 32 + b];
            out[((size_t)b * L_ + t) * P_ + blk * PPB + p] = s;
        }

        grid_bar(++barno);   // h_t visible chip-wide
    }
}

// ---------------------------------------------------------------------------
extern "C" void kernel_launch(void* const* d_in, const int* in_sizes, int n_in,
                              void* d_out, int out_size) {
    const float *x = nullptr, *Wih = nullptr, *Whh = nullptr, *Whr = nullptr;
    const float *bih = nullptr, *bhh = nullptr;
    for (int i = 0; i < n_in; i++) {
        const float* p = (const float*)d_in[i];
        long s = in_sizes[i];
        if      (s == (long)B_ * L_ * E_) x   = p;
        else if (s == (long)G4H_ * E_)    Wih = p;
        else if (s == (long)G4H_ * P_)    Whh = p;
        else if (s == (long)P_ * H_)      Whr = p;
        else if (s == G4H_) { if (!bih) bih = p; else bhh = p; }
    }
    // positional fallback
    if (!x)   x   = (const float*)d_in[0];
    if (!Wih) Wih = (const float*)d_in[1];
    if (!Whh) Whh = (const float*)d_in[2];
    if (!Whr) Whr = (const float*)d_in[3];
    if (!bih) bih = (const float*)d_in[4];
    if (!bhh) bhh = (const float*)d_in[5];
    float* out = (float*)d_out;

    cudaFuncSetAttribute(lstm_scan_kernel,
                         cudaFuncAttributeMaxDynamicSharedMemorySize, SMEM_BYTES);

    init_bar_kernel<<<1, 1>>>();

    dim3 ggrid(G4H_ / GBN, (B_ * L_) / GBM);  // (32, 128)
    gemm_xg_kernel<<<ggrid, 256>>>(x, Wih, bih, bhh);

    lstm_scan_kernel<<<NBLK, NTHR, SMEM_BYTES>>>(Whh, Whr, out);
}

// round 5
// speedup vs baseline: 1.4163x; 1.4163x over previous
#include <cuda_runtime.h>
#include <cuda_bf16.h>
#include <math.h>
#include <stdint.h>

// ---------------------------------------------------------------------------
// Problem dims
// ---------------------------------------------------------------------------
#define B_   32
#define L_   512
#define E_   1024
#define H_   1024
#define P_   512
#define G4H_ (4 * H_)
#define KB3  3072            // 3*E_ : [Ahi,Alo,Ahi] x [Whi,Whi,Wlo] split-bf16 GEMM

// ---------------------------------------------------------------------------
// Device-global scratch (no cudaMalloc allowed)
// ---------------------------------------------------------------------------
__device__ __nv_bfloat16 g_Abig[(size_t)B_ * L_ * KB3];   // 96 MB
__device__ __nv_bfloat16 g_Wbig[(size_t)G4H_ * KB3];      // 24 MB
__device__ float    g_xg[(size_t)B_ * L_ * G4H_];         // 256 MB  [b*L+t][4H]
__device__ float    g_m[H_ * B_];                         // [H][B]
__device__ unsigned g_arrive;
__device__ unsigned g_release;

__global__ void init_bar_kernel() { g_arrive = 0u; g_release = 0u; }

__device__ __forceinline__ uint32_t smem_u32(const void* p) {
    uint32_t a;
    asm("{ .reg .u64 t; cvta.to.shared.u64 t, %1; cvt.u32.u64 %0, t; }"
        : "=r"(a) : "l"(p));
    return a;
}

// ---------------------------------------------------------------------------
// Conversion kernels: fp32 -> split bf16 (hi + lo), K'=3072 layout
//   Abig[m]: [0,1024)=hi(x)  [1024,2048)=lo(x)  [2048,3072)=hi(x)
//   Wbig[n]: [0,1024)=hi(W)  [1024,2048)=hi(W)  [2048,3072)=lo(W)
// ---------------------------------------------------------------------------
__device__ __forceinline__ uint32_t pack2(__nv_bfloat16 a, __nv_bfloat16 b) {
    return (uint32_t)__bfloat16_as_ushort(a) | ((uint32_t)__bfloat16_as_ushort(b) << 16);
}

__global__ void __launch_bounds__(256) conv_a_kernel(const float* __restrict__ x) {
    size_t i4   = (size_t)blockIdx.x * 256 + threadIdx.x;  // grid = 16384 blocks
    size_t base = i4 * 4;
    int m = (int)(base >> 10);
    int k = (int)(base & 1023);
    float4 v = *reinterpret_cast<const float4*>(x + base);
    float f[4] = {v.x, v.y, v.z, v.w};
    __nv_bfloat16 h[4], lo[4];
#pragma unroll
    for (int i = 0; i < 4; i++) {
        h[i]  = __float2bfloat16(f[i]);
        lo[i] = __float2bfloat16(f[i] - __bfloat162float(h[i]));
    }
    uint2 hh = make_uint2(pack2(h[0], h[1]), pack2(h[2], h[3]));
    uint2 ll = make_uint2(pack2(lo[0], lo[1]), pack2(lo[2], lo[3]));
    __nv_bfloat16* row = g_Abig + (size_t)m * KB3;
    *reinterpret_cast<uint2*>(row + k)        = hh;
    *reinterpret_cast<uint2*>(row + 2048 + k) = hh;
    *reinterpret_cast<uint2*>(row + 1024 + k) = ll;
}

__global__ void __launch_bounds__(256) conv_w_kernel(const float* __restrict__ W) {
    size_t i4   = (size_t)blockIdx.x * 256 + threadIdx.x;  // grid = 4096 blocks
    size_t base = i4 * 4;
    int n = (int)(base >> 10);
    int k = (int)(base & 1023);
    float4 v = *reinterpret_cast<const float4*>(W + base);
    float f[4] = {v.x, v.y, v.z, v.w};
    __nv_bfloat16 h[4], lo[4];
#pragma unroll
    for (int i = 0; i < 4; i++) {
        h[i]  = __float2bfloat16(f[i]);
        lo[i] = __float2bfloat16(f[i] - __bfloat162float(h[i]));
    }
    uint2 hh = make_uint2(pack2(h[0], h[1]), pack2(h[2], h[3]));
    uint2 ll = make_uint2(pack2(lo[0], lo[1]), pack2(lo[2], lo[3]));
    __nv_bfloat16* row = g_Wbig + (size_t)n * KB3;
    *reinterpret_cast<uint2*>(row + k)        = hh;
    *reinterpret_cast<uint2*>(row + 1024 + k) = hh;
    *reinterpret_cast<uint2*>(row + 2048 + k) = ll;
}

// ---------------------------------------------------------------------------
// Phase 1 GEMM via mma.sync (bf16, sm_80+ path — works on base sm_100 target):
//   g_xg[m, n] = sum_k Abig[m,k] * Wbig[n,k] + bias[n]
// M=16384, N=4096, K=3072.  CTA tile 128x256, BK=32, 8 warps @ 64x64,
// 3-stage cp.async pipeline. Smem pitch 80B => conflict-free fragment LDS.
// ---------------------------------------------------------------------------
#define MT   128
#define NT   256
#define BK   32
#define NCH  (KB3 / BK)      // 96
#define ROWB 80              // bytes per smem row (32 bf16 + 8 pad)
#define STG  3

#define BIAS_OFF  0                       // 256 floats = 1024B
#define STG_OFF   1024
#define STG_BYTES (MT * ROWB + NT * ROWB) // 10240 + 20480 = 30720
#define A_OFF(s)  (STG_OFF + (s) * STG_BYTES)
#define B_OFF(s)  (A_OFF(s) + MT * ROWB)
#define GSMEM     (STG_OFF + STG * STG_BYTES)  // 93184

#define CP_ASYNC16(dst, src) \
    asm volatile("cp.async.cg.shared.global [%0], [%1], 16;" \
                 :: "r"(dst), "l"(src) : "memory")
#define CP_COMMIT()  asm volatile("cp.async.commit_group;" ::: "memory")
#define CP_WAIT2()   asm volatile("cp.async.wait_group 2;" ::: "memory")

__device__ __forceinline__ void mma16816(float* d, const uint32_t* a, const uint32_t* b) {
    asm volatile(
        "mma.sync.aligned.m16n8k16.row.col.f32.bf16.bf16.f32 "
        "{%0,%1,%2,%3}, {%4,%5,%6,%7}, {%8,%9}, {%0,%1,%2,%3};"
        : "+f"(d[0]), "+f"(d[1]), "+f"(d[2]), "+f"(d[3])
        : "r"(a[0]), "r"(a[1]), "r"(a[2]), "r"(a[3]), "r"(b[0]), "r"(b[1]));
}

__global__ void __launch_bounds__(256, 1)
gemm_mma_kernel(const float* __restrict__ bih, const float* __restrict__ bhh) {
    extern __shared__ char sm[];
    const uint32_t sb = smem_u32(sm);
    const int tid  = threadIdx.x;
    const int wid  = tid >> 5;
    const int lane = tid & 31;
    const int gid  = lane >> 2;     // 0..7
    const int tig  = lane & 3;      // 0..3
    const int wm   = wid >> 2;      // 0..1  (64-row half)
    const int wn   = wid & 3;       // 0..3  (64-col quarter)
    const int n0   = blockIdx.x * NT;
    const int m0   = blockIdx.y * MT;

    ((float*)(sm + BIAS_OFF))[tid] = bih[n0 + tid] + bhh[n0 + tid];

    const __nv_bfloat16* Ab = g_Abig + (size_t)m0 * KB3;
    const __nv_bfloat16* Bb = g_Wbig + (size_t)n0 * KB3;

    // cp.async staging: A = 128 rows x 4 x 16B, B = 256 rows x 4 x 16B
    auto load_stage = [&](int c, int s) {
#pragma unroll
        for (int p = 0; p < 2; ++p) {
            int u = tid + p * 256;
            int r = u >> 2, q = u & 3;
            CP_ASYNC16(sb + A_OFF(s) + r * ROWB + q * 16,
                       reinterpret_cast<const char*>(Ab + (size_t)r * KB3 + c * BK) + q * 16);
        }
#pragma unroll
        for (int p = 0; p < 4; ++p) {
            int u = tid + p * 256;
            int r = u >> 2, q = u & 3;
            CP_ASYNC16(sb + B_OFF(s) + r * ROWB + q * 16,
                       reinterpret_cast<const char*>(Bb + (size_t)r * KB3 + c * BK) + q * 16);
        }
    };

    float acc[4][8][4];
#pragma unroll
    for (int i = 0; i < 4; i++)
#pragma unroll
        for (int j = 0; j < 8; j++)
#pragma unroll
            for (int v = 0; v < 4; v++) acc[i][j][v] = 0.0f;

    load_stage(0, 0); CP_COMMIT();
    load_stage(1, 1); CP_COMMIT();

    const uint32_t a_base = sb + (wm * 64 + gid) * ROWB + tig * 4;
    const uint32_t b_base = sb + (wn * 64 + gid) * ROWB + tig * 4;

    for (int c = 0; c < NCH; ++c) {
        if (c + 2 < NCH) load_stage(c + 2, (c + 2) % STG);
        CP_COMMIT();
        CP_WAIT2();
        __syncthreads();

        const int buf = c % STG;
        const uint32_t abuf = a_base + A_OFF(buf);
        const uint32_t bbuf = b_base + B_OFF(buf);

#pragma unroll
        for (int ks = 0; ks < 2; ++ks) {
            uint32_t af[4][4];
#pragma unroll
            for (int mt = 0; mt < 4; ++mt) {
                uint32_t a0 = abuf + mt * (16 * ROWB) + ks * 32;
                asm volatile("ld.shared.b32 %0, [%1];" : "=r"(af[mt][0]) : "r"(a0));
                asm volatile("ld.shared.b32 %0, [%1];" : "=r"(af[mt][1]) : "r"(a0 + 8 * ROWB));
                asm volatile("ld.shared.b32 %0, [%1];" : "=r"(af[mt][2]) : "r"(a0 + 16));
                asm volatile("ld.shared.b32 %0, [%1];" : "=r"(af[mt][3]) : "r"(a0 + 8 * ROWB + 16));
            }
            uint32_t bf[8][2];
#pragma unroll
            for (int nt = 0; nt < 8; ++nt) {
                uint32_t b0 = bbuf + nt * (8 * ROWB) + ks * 32;
                asm volatile("ld.shared.b32 %0, [%1];" : "=r"(bf[nt][0]) : "r"(b0));
                asm volatile("ld.shared.b32 %0, [%1];" : "=r"(bf[nt][1]) : "r"(b0 + 16));
            }
#pragma unroll
            for (int mt = 0; mt < 4; ++mt)
#pragma unroll
                for (int nt = 0; nt < 8; ++nt)
                    mma16816(acc[mt][nt], af[mt], bf[nt]);
        }
        __syncthreads();
    }

    // Epilogue: direct row-major stores + bias
    const float* bias = (const float*)(sm + BIAS_OFF);
#pragma unroll
    for (int mt = 0; mt < 4; ++mt) {
#pragma unroll
        for (int nt = 0; nt < 8; ++nt) {
            int row0 = m0 + wm * 64 + mt * 16 + gid;
            int coll = wn * 64 + nt * 8 + tig * 2;   // local col in [0,256)
            int col  = n0 + coll;
            float2 v0 = make_float2(acc[mt][nt][0] + bias[coll],
                                    acc[mt][nt][1] + bias[coll + 1]);
            float2 v1 = make_float2(acc[mt][nt][2] + bias[coll],
                                    acc[mt][nt][3] + bias[coll + 1]);
            *reinterpret_cast<float2*>(&g_xg[(size_t)row0 * G4H_ + col])       = v0;
            *reinterpret_cast<float2*>(&g_xg[(size_t)(row0 + 8) * G4H_ + col]) = v1;
        }
    }
}

// ---------------------------------------------------------------------------
// Grid-wide barrier (persistent kernel, 128 co-resident CTAs).
// ---------------------------------------------------------------------------
__device__ __forceinline__ void grid_bar(unsigned k) {
    __syncthreads();
    if (threadIdx.x == 0) {
        __threadfence();
        unsigned prev = atomicAdd(&g_arrive, 1u);
        if (prev == k * (unsigned)gridDim.x - 1u) {
            *(volatile unsigned*)&g_release = k;
        } else {
            while (*(volatile unsigned*)&g_release < k) { }
            __threadfence();
        }
    }
    __syncthreads();
}

__device__ __forceinline__ float sigmoidf_(float x) {
    return 1.0f / (1.0f + __expf(-x));
}

// ---------------------------------------------------------------------------
// Phase 2: recurrent scan. 128 persistent CTAs x 256 threads.
// ---------------------------------------------------------------------------
#define NBLK 128
#define NTHR 256
#define JPB  8
#define PPB  4

#define HS_PITCH 36
#define HS_OFF   0
#define WS_OFF   (512 * HS_PITCH)
#define WR_OFF   (WS_OFF + 512 * HS_PITCH)
#define RED_OFF  (WR_OFF + H_ * 4)
#define SMEM_FLOATS (RED_OFF + 4 * 32 * 33)
#define SMEM_BYTES  (SMEM_FLOATS * 4)

__global__ void __launch_bounds__(NTHR, 1)
lstm_scan_kernel(const float* __restrict__ Whh,
                 const float* __restrict__ Whr,
                 float* __restrict__ out) {
    extern __shared__ float smem[];
    float* h_s  = smem + HS_OFF;
    float* w_s  = smem + WS_OFF;
    float* wr_s = smem + WR_OFF;
    float* red  = smem + RED_OFF;

    const int tid  = threadIdx.x;
    const int blk  = blockIdx.x;
    const int warp = tid >> 5;
    const int lane = tid & 31;

    for (int c = warp; c < 32; c += 8) {
        int gate = c >> 3, q = c & 7;
        const float* src = Whh + (size_t)(gate * H_ + blk * JPB + q) * P_;
        for (int k = lane; k < P_; k += 32) w_s[k * HS_PITCH + c] = src[k];
    }
    for (int idx = tid; idx < PPB * H_; idx += NTHR) {
        int pp = idx >> 10;
        int k  = idx & (H_ - 1);
        wr_s[k * 4 + pp] = Whr[(size_t)(blk * PPB + pp) * H_ + k];
    }
    __syncthreads();

    float cst = 0.0f;
    const int cb = tid >> 3;
    const int cq = tid & 7;

    const int g4 = tid >> 6;
    const int id = tid & 63;
    const int ty = id >> 3;
    const int tx = id & 7;

    unsigned barno = 0;

    for (int t = 0; t < L_; ++t) {
        float xgv[4];
#pragma unroll
        for (int gi = 0; gi < 4; ++gi)
            xgv[gi] = __ldg(&g_xg[((size_t)cb * L_ + t) * G4H_ + gi * H_ + blk * JPB + cq]);

        float acc[4][4];
#pragma unroll
        for (int i = 0; i < 4; i++)
#pragma unroll
            for (int j = 0; j < 4; j++) acc[i][j] = 0.0f;

        if (t > 0) {
            for (int idx = tid; idx < B_ * P_; idx += NTHR) {
                int b = idx >> 9;
                int k = idx & (P_ - 1);
                h_s[k * HS_PITCH + b] =
                    __ldcg(out + ((size_t)b * L_ + (t - 1)) * P_ + k);
            }
            __syncthreads();

            const int k0 = g4 * 128;
#pragma unroll 4
            for (int kk = 0; kk < 128; ++kk) {
                int k = k0 + kk;
                float4 hv = *reinterpret_cast<const float4*>(&h_s[k * HS_PITCH + 4 * ty]);
                float4 wv = *reinterpret_cast<const float4*>(&w_s[k * HS_PITCH + 4 * tx]);
                float hb[4] = {hv.x, hv.y, hv.z, hv.w};
                float wb[4] = {wv.x, wv.y, wv.z, wv.w};
#pragma unroll
                for (int i = 0; i < 4; i++)
#pragma unroll
                    for (int j = 0; j < 4; j++) acc[i][j] += hb[i] * wb[j];
            }
        }

#pragma unroll
        for (int i = 0; i < 4; i++)
#pragma unroll
            for (int j = 0; j < 4; j++)
                red[(g4 * 32 + 4 * ty + i) * 33 + 4 * tx + j] = acc[i][j];
        __syncthreads();

        {
            float gsum[4];
#pragma unroll
            for (int gi = 0; gi < 4; ++gi) {
                int c = gi * 8 + cq;
                float s = red[(0 * 32 + cb) * 33 + c] + red[(1 * 32 + cb) * 33 + c] +
                          red[(2 * 32 + cb) * 33 + c] + red[(3 * 32 + cb) * 33 + c];
                gsum[gi] = s + xgv[gi];
            }
            float ig = sigmoidf_(gsum[0]);
            float fg = sigmoidf_(gsum[1]);
            float gg = tanhf(gsum[2]);
            float og = sigmoidf_(gsum[3]);
            cst = fg * cst + ig * gg;
            float m = og * tanhf(cst);
            g_m[(blk * JPB + cq) * B_ + cb] = m;
        }

        grid_bar(++barno);

        float pa[4] = {0.0f, 0.0f, 0.0f, 0.0f};
        {
            const int kbeg = warp * 128;
#pragma unroll 16
            for (int k = kbeg; k < kbeg + 128; ++k) {
                float  mv = __ldcg(&g_m[k * B_ + lane]);
                float4 wv = *reinterpret_cast<const float4*>(&wr_s[k * 4]);
                pa[0] += mv * wv.x;
                pa[1] += mv * wv.y;
                pa[2] += mv * wv.z;
                pa[3] += mv * wv.w;
            }
        }
#pragma unroll
        for (int p = 0; p < 4; p++) red[(warp * 4 + p) * 32 + lane] = pa[p];
        __syncthreads();
        if (tid < 128) {
            int p = tid >> 5;
            int b = tid & 31;
            float s = 0.0f;
#pragma unroll
            for (int w = 0; w < 8; w++) s += red[(w * 4 + p) * 32 + b];
            out[((size_t)b * L_ + t) * P_ + blk * PPB + p] = s;
        }

        grid_bar(++barno);
    }
}

// ---------------------------------------------------------------------------
extern "C" void kernel_launch(void* const* d_in, const int* in_sizes, int n_in,
                              void* d_out, int out_size) {
    const float *x = nullptr, *Wih = nullptr, *Whh = nullptr, *Whr = nullptr;
    const float *bih = nullptr, *bhh = nullptr;
    for (int i = 0; i < n_in; i++) {
        const float* p = (const float*)d_in[i];
        long s = in_sizes[i];
        if      (s == (long)B_ * L_ * E_) x   = p;
        else if (s == (long)G4H_ * E_)    Wih = p;
        else if (s == (long)G4H_ * P_)    Whh = p;
        else if (s == (long)P_ * H_)      Whr = p;
        else if (s == G4H_) { if (!bih) bih = p; else bhh = p; }
    }
    if (!x)   x   = (const float*)d_in[0];
    if (!Wih) Wih = (const float*)d_in[1];
    if (!Whh) Whh = (const float*)d_in[2];
    if (!Whr) Whr = (const float*)d_in[3];
    if (!bih) bih = (const float*)d_in[4];
    if (!bhh) bhh = (const float*)d_in[5];
    float* out = (float*)d_out;

    cudaFuncSetAttribute(gemm_mma_kernel,
                         cudaFuncAttributeMaxDynamicSharedMemorySize, GSMEM);
    cudaFuncSetAttribute(lstm_scan_kernel,
                         cudaFuncAttributeMaxDynamicSharedMemorySize, SMEM_BYTES);

    init_bar_kernel<<<1, 1>>>();
    conv_a_kernel<<<(B_ * L_ * E_) / (256 * 4), 256>>>(x);
    conv_w_kernel<<<(G4H_ * E_) / (256 * 4), 256>>>(Wih);

    dim3 ggrid(G4H_ / NT, (B_ * L_) / MT);   // (16, 128)
    gemm_mma_kernel<<<ggrid, 256, GSMEM>>>(bih, bhh);

    lstm_scan_kernel<<<NBLK, NTHR, SMEM_BYTES>>>(Whh, Whr, out);
}